// round 6
// baseline (speedup 1.0000x reference)
#include <cuda_runtime.h>

// Local cost volume (SpatialCorrelationSampler, kernel_size=1, patch 9x9):
// out[b, p, y, x] = sum_c t1[b,c,y,x] * t2[b,c,y+di,x+dj-?],  p=(di+4)*9+(dj+4)
// t1,t2 [4,128,128,256] f32 -> out [4,81,128,256] f32.
//
// Block = one (batch, y) full row. 9 warps; warp w owns di = w-4.
// Lane owns 8 px. Packed fma.rn.f32x2. Odd dj use +1-shifted accumulator
// basis so B operands are the SAME aligned pairs as even dj. Smem uses a
// 16B-granule swizzle g^((g>>3)&1) (involution) for conflict-free LDS.128
// at 32B lane stride. x=0 odd-dj edge handled by one extra accumulator.

#define CH 128
#define HH 128
#define WW 256
#define MD 4
#define DD 9
#define CC 4
#define T2C 264           // 66 granules: g0 pad, g1..g64 data, g65 pad
#define T2G 66
#define T1C 256
#define HW (HH*WW)
#define NTHREADS 288
#define NCHUNK 32
#define STAGES 2

#define T1_STG (CC*T1C)        // 1024 floats
#define T2_STG (CC*DD*T2C)     // 9504 floats
#define STG_FLOATS (T1_STG + T2_STG)
#define SMEM_BYTES (STAGES*STG_FLOATS*4)   // 84224 B

#define SWIZ(g) ((g) ^ (((g) >> 3) & 1))

typedef unsigned long long u64;

__device__ __forceinline__ u64 pk(float lo, float hi) {
    u64 r; asm("mov.b64 %0, {%1,%2};" : "=l"(r) : "f"(lo), "f"(hi)); return r;
}
__device__ __forceinline__ void fma2(u64 &d, u64 a, u64 b) {
    asm("fma.rn.f32x2 %0, %1, %2, %0;" : "+l"(d) : "l"(a), "l"(b));
}
__device__ __forceinline__ float2 upk(u64 v) {
    float lo, hi; asm("mov.b64 {%0,%1}, %2;" : "=f"(lo), "=f"(hi) : "l"(v));
    return make_float2(lo, hi);
}
__device__ __forceinline__ void cpasync16(unsigned smem_addr, const void* gptr) {
    asm volatile("cp.async.cg.shared.global [%0], [%1], 16;" ::
                 "r"(smem_addr), "l"(gptr));
}

__global__ __launch_bounds__(NTHREADS, 2)
void corr_volume_kernel(const float* __restrict__ t1,
                        const float* __restrict__ t2,
                        float* __restrict__ out)
{
    extern __shared__ float sm[];
    float* s_t1 = sm;                       // [STAGES][CC][T1C]
    float* s_t2 = sm + STAGES * T1_STG;     // [STAGES][CC][DD][T2C]

    const int tid   = threadIdx.x;
    const int wid   = tid >> 5;             // 0..8 : di row
    const int lane  = tid & 31;
    const int batch = blockIdx.x >> 7;
    const int y     = blockIdx.x & (HH - 1);

    const int gy = y + wid - MD;
    const bool vrow = (unsigned)gy < (unsigned)HH;   // warp-uniform
    const float* t2row = t2 + (size_t)batch * CH * HW + (size_t)(vrow ? gy : 0) * WW;
    const float* t1row = t1 + (size_t)batch * CH * HW + (size_t)y * WW;

    // ---- one-time zero of pad regions (both stages) ----
    {
        const float4 z = make_float4(0.f, 0.f, 0.f, 0.f);
        #pragma unroll
        for (int st = 0; st < STAGES; st++)
            #pragma unroll
            for (int cc = 0; cc < CC; cc++) {
                float* row = s_t2 + (size_t)st * T2_STG + (cc * DD + wid) * T2C;
                if (vrow) {
                    if (lane == 0) *(float4*)&row[0]       = z;  // granule 0
                    if (lane == 1) *(float4*)&row[65 * 4]  = z;  // granule 65
                } else {
                    for (int g = lane; g < T2G; g += 32)
                        *(float4*)&row[g * 4] = z;
                }
            }
    }

    u64 acc[DD][4];
    #pragma unroll
    for (int d = 0; d < DD; d++)
        #pragma unroll
        for (int k = 0; k < 4; k++) acc[d][k] = 0ull;
    u64 acc_e = 0ull;     // x=0 edge: (dj=5, dj=7)

    // ---- loader constants ----
    // t2: storage granules p1,p2 (linear: conflict-free STS); content = logical
    // granule SWIZ(p); src gx offset = (SWIZ(p)-1)*4 floats.
    const int p1 = 1 + lane, p2 = 33 + lane;
    const int q1 = SWIZ(p1), q2 = SWIZ(p2);
    const unsigned t2base = (unsigned)__cvta_generic_to_shared(s_t2);
    const unsigned t2d1 = t2base + (unsigned)(wid * T2C + p1 * 4) * 4;
    const unsigned t2d2 = t2base + (unsigned)(wid * T2C + p2 * 4) * 4;
    const int t2s1 = (q1 - 1) * 4;   // float offset in global row
    const int t2s2 = (q2 - 1) * 4;
    // t1: storage granules lane, lane+32; content logical SWIZ(p); warps 0..3.
    const unsigned t1base = (unsigned)__cvta_generic_to_shared(s_t1);
    const unsigned t1d1 = t1base + (unsigned)(wid * T1C + lane * 4) * 4;
    const unsigned t1d2 = t1base + (unsigned)(wid * T1C + (lane + 32) * 4) * 4;
    const int t1s1 = SWIZ(lane) * 4;
    const int t1s2 = SWIZ(lane + 32) * 4;

    auto issue = [&](int chunk) {
        const int c0 = chunk * CC;
        const int st = chunk & 1;
        if (wid < CC) {
            const float* src = t1row + (size_t)(c0 + wid) * HW;
            cpasync16(t1d1 + st * (T1_STG * 4), &src[t1s1]);
            cpasync16(t1d2 + st * (T1_STG * 4), &src[t1s2]);
        }
        if (vrow) {
            #pragma unroll
            for (int cc = 0; cc < CC; cc++) {
                const float* src = t2row + (size_t)(c0 + cc) * HW;
                unsigned off = (unsigned)(st * T2_STG + cc * (DD * T2C)) * 4;
                cpasync16(t2d1 + off, &src[t2s1]);
                cpasync16(t2d2 + off, &src[t2s2]);
            }
        }
        asm volatile("cp.async.commit_group;");
    };

    // compute-side swizzled byte offsets (per-thread constants)
    const int gw = 2 * lane;      // first logical granule of this lane's window
    const unsigned o_w0 = SWIZ(gw + 0) * 16u;
    const unsigned o_w1 = SWIZ(gw + 1) * 16u;
    const unsigned o_w2 = SWIZ(gw + 2) * 16u;
    const unsigned o_w3 = SWIZ(gw + 3) * 16u;
    const unsigned o_a0 = SWIZ(gw + 0) * 16u;
    const unsigned o_a1 = SWIZ(gw + 1) * 16u;

    issue(0);

    for (int it = 0; it < NCHUNK; it++) {
        const int st = it & 1;
        asm volatile("cp.async.wait_group 0;");
        __syncthreads();                  // chunk `it` visible; other stage free
        if (it + 1 < NCHUNK) issue(it + 1);

        #pragma unroll
        for (int cc = 0; cc < CC; cc++) {
            const char* t1r = (const char*)(s_t1 + (size_t)st * T1_STG + cc * T1C);
            float4 f0 = *(const float4*)(t1r + o_a0);
            float4 f1 = *(const float4*)(t1r + o_a1);
            float a8 = __shfl_down_sync(0xffffffffu, f0.x, 1);

            u64 A0 = pk(f0.x, f0.y), A1 = pk(f0.z, f0.w);
            u64 A2 = pk(f1.x, f1.y), A3 = pk(f1.z, f1.w);
            u64 S0 = pk(f0.y, f0.z), S1 = pk(f0.w, f1.x);
            u64 S2 = pk(f1.y, f1.z), S3 = pk(f1.w, a8);

            const float* t2f = s_t2 + (size_t)st * T2_STG + (cc * DD + wid) * T2C;
            const char*  t2r = (const char*)t2f;
            ulonglong2 w0 = *(const ulonglong2*)(t2r + o_w0);
            ulonglong2 w1 = *(const ulonglong2*)(t2r + o_w1);
            ulonglong2 w2 = *(const ulonglong2*)(t2r + o_w2);
            ulonglong2 w3 = *(const ulonglong2*)(t2r + o_w3);
            u64 P0 = w0.x, P1 = w0.y, P2 = w1.x, P3 = w1.y;
            u64 P4 = w2.x, P5 = w2.y, P6 = w3.x, P7 = w3.y;

            // even dj (natural basis): acc[dj][k] += A_k * P[k + dj/2]
            fma2(acc[0][0], A0, P0); fma2(acc[0][1], A1, P1);
            fma2(acc[0][2], A2, P2); fma2(acc[0][3], A3, P3);
            fma2(acc[2][0], A0, P1); fma2(acc[2][1], A1, P2);
            fma2(acc[2][2], A2, P3); fma2(acc[2][3], A3, P4);
            fma2(acc[4][0], A0, P2); fma2(acc[4][1], A1, P3);
            fma2(acc[4][2], A2, P4); fma2(acc[4][3], A3, P5);
            fma2(acc[6][0], A0, P3); fma2(acc[6][1], A1, P4);
            fma2(acc[6][2], A2, P5); fma2(acc[6][3], A3, P6);
            fma2(acc[8][0], A0, P4); fma2(acc[8][1], A1, P5);
            fma2(acc[8][2], A2, P6); fma2(acc[8][3], A3, P7);
            // odd dj (+1 basis): acc[dj][k] += S_k * P[k + (dj+1)/2]
            fma2(acc[1][0], S0, P1); fma2(acc[1][1], S1, P2);
            fma2(acc[1][2], S2, P3); fma2(acc[1][3], S3, P4);
            fma2(acc[3][0], S0, P2); fma2(acc[3][1], S1, P3);
            fma2(acc[3][2], S2, P4); fma2(acc[3][3], S3, P5);
            fma2(acc[5][0], S0, P3); fma2(acc[5][1], S1, P4);
            fma2(acc[5][2], S2, P5); fma2(acc[5][3], S3, P6);
            fma2(acc[7][0], S0, P4); fma2(acc[7][1], S1, P5);
            fma2(acc[7][2], S2, P6); fma2(acc[7][3], S3, P7);

            // x=0 edge (odd dj 5,7): t2 gx=1,3 -> storage cols 5,7 (granule 1)
            float e1  = t2f[5], e3 = t2f[7];
            float t10 = ((const float*)t1r)[0];
            fma2(acc_e, pk(t10, t10), pk(e1, e3));
        }
    }

    // ---- epilogue ----
    const int xl = lane * 8;
    float2 e = upk(acc_e);
    size_t obase = (((size_t)batch * 81 + (size_t)wid * DD) * HH + y) * WW + xl;
    #pragma unroll
    for (int dj = 0; dj < DD; dj++) {
        float2 c0 = upk(acc[dj][0]), c1 = upk(acc[dj][1]);
        float2 c2 = upk(acc[dj][2]), c3 = upk(acc[dj][3]);
        float4 o0, o1;
        if ((dj & 1) == 0) {
            o0 = make_float4(c0.x, c0.y, c1.x, c1.y);
            o1 = make_float4(c2.x, c2.y, c3.x, c3.y);
        } else {
            float cprev = __shfl_up_sync(0xffffffffu, c3.y, 1);
            if (lane == 0)
                cprev = (dj == 5) ? e.x : (dj == 7) ? e.y : 0.0f;
            o0 = make_float4(cprev, c0.x, c0.y, c1.x);
            o1 = make_float4(c1.y, c2.x, c2.y, c3.x);
        }
        *(float4*)&out[obase + (size_t)dj * HW]     = o0;
        *(float4*)&out[obase + (size_t)dj * HW + 4] = o1;
    }
}

extern "C" void kernel_launch(void* const* d_in, const int* in_sizes, int n_in,
                              void* d_out, int out_size)
{
    const float* t1 = (const float*)d_in[0];
    const float* t2 = (const float*)d_in[1];
    float* out = (float*)d_out;
    cudaFuncSetAttribute(corr_volume_kernel,
                         cudaFuncAttributeMaxDynamicSharedMemorySize, SMEM_BYTES);
    corr_volume_kernel<<<4 * HH, NTHREADS, SMEM_BYTES>>>(t1, t2, out);
}

// round 8
// speedup vs baseline: 1.0714x; 1.0714x over previous
#include <cuda_runtime.h>

// Local cost volume (SpatialCorrelationSampler, kernel_size=1, patch 9x9):
// out[b, p, y, x] = sum_c t1[b,c,y,x] * t2[b,c,y+di,x+dj],  p=(di+4)*9+(dj+4)
// t1,t2 [4,128,128,256] f32 -> out [4,81,128,256] f32.
//
// Block = (batch, y, x-tile of 128). 9 warps; warp w owns di = w-4.
// Each warp PRODUCES exactly the t2 halo row it CONSUMES -> fully
// warp-autonomous cp.async pipeline into a private smem region, synced with
// wait_group + __syncwarp only. t1 read via direct LDG (L1-shared across the
// 9 warps). ZERO __syncthreads. Packed fma.rn.f32x2, 4 px/lane, 3 CTAs/SM.

#define CH 128
#define HH 128
#define WW 256
#define MD 4
#define DD 9
#define CC 4
#define XT 128
#define T2C 136           // 34 granules of 4 floats
#define HW (HH*WW)
#define NTHREADS 288
#define NCHUNK 32
#define STAGES 3

// smem: [STAGES][9 warps][CC][T2C] floats
#define WARP_STG (CC * T2C)           // 544 floats
#define T2_STG   (DD * WARP_STG)      // 4896 floats
#define SMEM_BYTES (STAGES * T2_STG * 4)   // 58752 B

typedef unsigned long long u64;

__device__ __forceinline__ u64 pk(float lo, float hi) {
    u64 r; asm("mov.b64 %0, {%1,%2};" : "=l"(r) : "f"(lo), "f"(hi)); return r;
}
__device__ __forceinline__ void fma2(u64 &d, u64 a, u64 b) {
    asm("fma.rn.f32x2 %0, %1, %2, %0;" : "+l"(d) : "l"(a), "l"(b));
}
__device__ __forceinline__ float2 upk(u64 v) {
    float lo, hi; asm("mov.b64 {%0,%1}, %2;" : "=f"(lo), "=f"(hi) : "l"(v));
    return make_float2(lo, hi);
}
__device__ __forceinline__ void cpasync16(unsigned smem_addr, const void* gptr) {
    asm volatile("cp.async.cg.shared.global [%0], [%1], 16;" ::
                 "r"(smem_addr), "l"(gptr));
}

__global__ __launch_bounds__(NTHREADS, 3)
void corr_volume_kernel(const float* __restrict__ t1,
                        const float* __restrict__ t2,
                        float* __restrict__ out)
{
    extern __shared__ float sm[];   // [STAGES][DD][CC][T2C]

    const int tid   = threadIdx.x;
    const int wid   = tid >> 5;            // 0..8 : di row
    const int lane  = tid & 31;
    const int blk   = blockIdx.x;          // 0..1023
    const int xt    = blk & 1;
    const int y     = (blk >> 1) & (HH - 1);
    const int batch = blk >> 8;
    const int x0    = xt * XT;

    const int gy = y + wid - MD;
    const bool vrow = (unsigned)gy < (unsigned)HH;     // warp-uniform

    // this warp's private smem row (per stage)
    float* myrow0 = sm + wid * WARP_STG;               // stage 0 base

    // halo chunk geometry: storage col 4h holds gx = x0-4+4h; valid h in
    // [lo, lo+33); exactly one pad chunk per row.
    const int lo   = (xt == 0) ? 1 : 0;
    const int hpad = (xt == 0) ? 0 : 33;

    // ---- one-time zero of pad (own region only; no CTA sync needed) ----
    if (vrow) {
        if (lane == 0) {
            #pragma unroll
            for (int st = 0; st < STAGES; st++)
                #pragma unroll
                for (int cc = 0; cc < CC; cc++)
                    *(float4*)&myrow0[st * T2_STG + cc * T2C + 4 * hpad] =
                        make_float4(0.f, 0.f, 0.f, 0.f);
        }
    } else {
        #pragma unroll
        for (int st = 0; st < STAGES; st++)
            #pragma unroll
            for (int cc = 0; cc < CC; cc++) {
                float* row = myrow0 + st * T2_STG + cc * T2C;
                *(float4*)&row[4 * lane] = make_float4(0.f, 0.f, 0.f, 0.f);
                if (lane < 2)
                    *(float4*)&row[4 * (32 + lane)] = make_float4(0.f, 0.f, 0.f, 0.f);
            }
    }

    u64 acc[DD][2];
    #pragma unroll
    for (int d = 0; d < DD; d++) { acc[d][0] = 0ull; acc[d][1] = 0ull; }

    const int xl = lane * 4;

    // ---- loader state (pointer-incremented, no per-chunk multiplies) ----
    // lane l fills chunk h1 = lo + l; lane 0 also fills h2 = lo + 32.
    const int h1 = lo + lane;
    const int h2 = lo + 32;
    const unsigned smbase = (unsigned)__cvta_generic_to_shared(myrow0);
    const unsigned d1 = smbase + (unsigned)(4 * h1) * 4;
    const unsigned d2 = smbase + (unsigned)(4 * h2) * 4;
    // global source pointers for chunk 0 (advance by CC*HW per chunk)
    const float* s1 = t2 + (size_t)batch * CH * HW + (size_t)(vrow ? gy : 0) * WW
                         + (x0 - 4 + 4 * h1);
    const float* s2 = s1 + 4 * (h2 - h1);

    // t1 source (advance by CC*HW per chunk)
    const float* a1 = t1 + (size_t)batch * CH * HW + (size_t)y * WW + x0 + xl;

    const float* s1i = s1;   // issue-side running pointers (prefetch ahead)
    const float* s2i = s2;

    auto issue = [&](int chunk) {
        if (vrow) {
            const unsigned so = (unsigned)((chunk % STAGES) * T2_STG) * 4;
            #pragma unroll
            for (int cc = 0; cc < CC; cc++) {
                const unsigned co = so + (unsigned)(cc * T2C) * 4;
                cpasync16(d1 + co, s1i + (size_t)cc * HW);
                if (lane == 0) cpasync16(d2 + co, s2i + (size_t)cc * HW);
            }
            s1i += (size_t)CC * HW;
            s2i += (size_t)CC * HW;
        }
        asm volatile("cp.async.commit_group;");
    };

    issue(0);
    issue(1);

    for (int it = 0; it < NCHUNK; it++) {
        asm volatile("cp.async.wait_group 1;");
        __syncwarp();                       // chunk `it` visible warp-wide;
                                            // all lanes done reading stage it-1
        if (it + 2 < NCHUNK) issue(it + 2);

        const float* b_t2 = myrow0 + (it % STAGES) * T2_STG;

        #pragma unroll
        for (int cc = 0; cc < CC; cc++) {
            float4 a = __ldg((const float4*)(a1 + (size_t)cc * HW));
            u64 A0 = pk(a.x, a.y), A1 = pk(a.z, a.w);

            const float* tr = b_t2 + cc * T2C + xl;
            float4 v0 = *(const float4*)&tr[0];
            float4 v1 = *(const float4*)&tr[4];
            float4 v2 = *(const float4*)&tr[8];

            u64 P[6];
            P[0] = pk(v0.x, v0.y); P[1] = pk(v0.z, v0.w);
            P[2] = pk(v1.x, v1.y); P[3] = pk(v1.z, v1.w);
            P[4] = pk(v2.x, v2.y); P[5] = pk(v2.z, v2.w);
            u64 Q[5];
            Q[0] = pk(v0.y, v0.z); Q[1] = pk(v0.w, v1.x);
            Q[2] = pk(v1.y, v1.z); Q[3] = pk(v1.w, v2.x);
            Q[4] = pk(v2.y, v2.z);

            #pragma unroll
            for (int dj = 0; dj < DD; dj++) {
                const int h = dj >> 1;
                if ((dj & 1) == 0) {
                    fma2(acc[dj][0], A0, P[h + 0]);
                    fma2(acc[dj][1], A1, P[h + 1]);
                } else {
                    fma2(acc[dj][0], A0, Q[h + 0]);
                    fma2(acc[dj][1], A1, Q[h + 1]);
                }
            }
        }
        a1 += (size_t)CC * HW;
    }

    // ---- write out: p = wid*9 + dj ----
    size_t obase = (((size_t)batch * 81 + (size_t)wid * DD) * HH + y) * WW + x0 + xl;
    #pragma unroll
    for (int dj = 0; dj < DD; dj++) {
        float2 p0 = upk(acc[dj][0]), p1 = upk(acc[dj][1]);
        *(float4*)&out[obase + (size_t)dj * HW] = make_float4(p0.x, p0.y, p1.x, p1.y);
    }
}

extern "C" void kernel_launch(void* const* d_in, const int* in_sizes, int n_in,
                              void* d_out, int out_size)
{
    const float* t1 = (const float*)d_in[0];
    const float* t2 = (const float*)d_in[1];
    float* out = (float*)d_out;
    cudaFuncSetAttribute(corr_volume_kernel,
                         cudaFuncAttributeMaxDynamicSharedMemorySize, SMEM_BYTES);
    corr_volume_kernel<<<2 * 4 * HH, NTHREADS, SMEM_BYTES>>>(t1, t2, out);
}

// round 9
// speedup vs baseline: 1.1188x; 1.0442x over previous
#include <cuda_runtime.h>

// Local cost volume (SpatialCorrelationSampler, kernel_size=1, patch 9x9):
// out[b, p, y, x] = sum_c t1[b,c,y,x] * t2[b,c,y+di,x+dj],  p=(di+4)*9+(dj+4)
// t1,t2 [4,128,128,256] f32 -> out [4,81,128,256] f32.
//
// R4 structure (best kernel) with the copy engine swapped: instead of 425
// 16B cp.async.cg per chunk (LDGSTS issue-bound), ~40 cp.async.bulk row
// copies per chunk complete via mbarrier expect_tx/complete_tx. 9 warps,
// warp w owns di=w-4; lane owns 4 px; packed fma.rn.f32x2; 3 stages.

#define CH 128
#define HH 128
#define WW 256
#define MD 4
#define DD 9
#define CC 4
#define XT 128
#define T2C 136           // halo row: 136 floats (132 data + 4 pad)
#define HW (HH*WW)
#define NTHREADS 288
#define NCHUNK 32
#define STAGES 3

#define T1_STG (CC*XT)          // 512 floats
#define T2_STG (CC*DD*T2C)      // 4896 floats
#define SM_T1_OFF 8             // float offset (mbars in floats 0..7)
#define SM_T2_OFF (SM_T1_OFF + STAGES*T1_STG)
#define SMEM_BYTES ((SM_T2_OFF + STAGES*T2_STG)*4)   // 64,928 B

typedef unsigned long long u64;

__device__ __forceinline__ u64 pk(float lo, float hi) {
    u64 r; asm("mov.b64 %0, {%1,%2};" : "=l"(r) : "f"(lo), "f"(hi)); return r;
}
__device__ __forceinline__ void fma2(u64 &d, u64 a, u64 b) {
    asm("fma.rn.f32x2 %0, %1, %2, %0;" : "+l"(d) : "l"(a), "l"(b));
}
__device__ __forceinline__ float2 upk(u64 v) {
    float lo, hi; asm("mov.b64 {%0,%1}, %2;" : "=f"(lo), "=f"(hi) : "l"(v));
    return make_float2(lo, hi);
}
__device__ __forceinline__ void bulkcp(unsigned dst, const void* src,
                                       unsigned bytes, unsigned mbar) {
    asm volatile(
        "cp.async.bulk.shared::cluster.global.mbarrier::complete_tx::bytes "
        "[%0], [%1], %2, [%3];"
        :: "r"(dst), "l"(src), "r"(bytes), "r"(mbar) : "memory");
}
__device__ __forceinline__ void mbar_init(unsigned mbar, unsigned cnt) {
    asm volatile("mbarrier.init.shared::cta.b64 [%0], %1;"
                 :: "r"(mbar), "r"(cnt) : "memory");
}
__device__ __forceinline__ void mbar_expect_arrive(unsigned mbar, unsigned bytes) {
    asm volatile("mbarrier.arrive.expect_tx.shared::cta.b64 _, [%0], %1;"
                 :: "r"(mbar), "r"(bytes) : "memory");
}
__device__ __forceinline__ void mbar_arrive(unsigned mbar) {
    asm volatile("mbarrier.arrive.shared::cta.b64 _, [%0];"
                 :: "r"(mbar) : "memory");
}
__device__ __forceinline__ void mbar_wait(unsigned mbar, unsigned phase) {
    asm volatile(
        "{\n\t"
        ".reg .pred P;\n\t"
        "WAIT_%=:\n\t"
        "mbarrier.try_wait.parity.shared::cta.b64 P, [%0], %1;\n\t"
        "@P bra.uni DONE_%=;\n\t"
        "bra.uni WAIT_%=;\n\t"
        "DONE_%=:\n\t"
        "}" :: "r"(mbar), "r"(phase) : "memory");
}

__global__ __launch_bounds__(NTHREADS, 3)
void corr_volume_kernel(const float* __restrict__ t1,
                        const float* __restrict__ t2,
                        float* __restrict__ out)
{
    extern __shared__ float sm[];
    float* s_t1 = sm + SM_T1_OFF;       // [STAGES][CC][XT]
    float* s_t2 = sm + SM_T2_OFF;       // [STAGES][CC][DD][T2C]

    const int tid   = threadIdx.x;
    const int wid   = tid >> 5;          // 0..8 : di row
    const int lane  = tid & 31;
    const int blk   = blockIdx.x;        // 0..1023
    const int xt    = blk & 1;
    const int y     = (blk >> 1) & (HH - 1);
    const int batch = blk >> 8;
    const int x0    = xt * XT;

    const int gy = y + wid - MD;
    const bool vrow = (unsigned)gy < (unsigned)HH;    // warp-uniform

    // halo copy geometry: dst col j holds gx = x0 + j - 4.
    // valid gx span is always 132 floats (528 B):
    //   xt=0: gx [0,132)   -> dst cols [4,136),  src float offset 0
    //   xt=1: gx [124,256) -> dst cols [0,132),  src float offset 124
    const int dstcol = (xt == 0) ? 4 : 0;
    const int xs     = (xt == 0) ? 0 : 124;

    const unsigned mb0 = (unsigned)__cvta_generic_to_shared(sm);  // 3 mbars
    const unsigned t1b = (unsigned)__cvta_generic_to_shared(s_t1);
    const unsigned t2b = (unsigned)__cvta_generic_to_shared(s_t2);

    // ---- init mbarriers (9 arrivals: lane0 of each warp) ----
    if (tid < STAGES) mbar_init(mb0 + tid * 8, DD);

    // ---- one-time zero of constant pad regions (all stages) ----
    {
        const float4 z = make_float4(0.f, 0.f, 0.f, 0.f);
        #pragma unroll
        for (int st = 0; st < STAGES; st++)
            #pragma unroll
            for (int cc = 0; cc < CC; cc++) {
                float* row = s_t2 + (size_t)st * T2_STG + (cc * DD + wid) * T2C;
                if (vrow) {
                    if (lane == 0)
                        *(float4*)&row[(xt == 0) ? 0 : 132] = z;
                } else {
                    *(float4*)&row[4 * lane] = z;               // cols 0..127
                    if (lane < 2) *(float4*)&row[128 + 4 * lane] = z; // 128..135
                }
            }
    }
    __syncthreads();
    asm volatile("fence.proxy.async.shared::cta;" ::: "memory");

    u64 acc[DD][2];
    #pragma unroll
    for (int d = 0; d < DD; d++) { acc[d][0] = 0ull; acc[d][1] = 0ull; }

    const int xl = lane * 4;

    // producer-side running pointers (advance CC*HW per issued chunk)
    const float* t2src = t2 + (size_t)batch * CH * HW
                            + (size_t)(vrow ? gy : 0) * WW + xs;
    const float* t1src = t1 + (size_t)batch * CH * HW + (size_t)y * WW + x0;
    int prod_stage = 0;

    const unsigned t2row_bytes = 132 * 4;   // 528
    const unsigned t1row_bytes = XT * 4;    // 512
    const unsigned my_bytes = (vrow ? 4 * t2row_bytes : 0)
                            + (wid == 0 ? 4 * t1row_bytes : 0);

    auto issue = [&]() {
        if (lane == 0) {
            const unsigned mb = mb0 + prod_stage * 8;
            if (my_bytes) mbar_expect_arrive(mb, my_bytes);
            else          mbar_arrive(mb);
            if (vrow) {
                unsigned d2 = t2b + (unsigned)(prod_stage * T2_STG
                                   + wid * T2C + dstcol) * 4;
                #pragma unroll
                for (int cc = 0; cc < CC; cc++)
                    bulkcp(d2 + (unsigned)(cc * (DD * T2C)) * 4,
                           t2src + (size_t)cc * HW, t2row_bytes, mb);
            }
            if (wid == 0) {
                unsigned d1 = t1b + (unsigned)(prod_stage * T1_STG) * 4;
                #pragma unroll
                for (int cc = 0; cc < CC; cc++)
                    bulkcp(d1 + (unsigned)(cc * XT) * 4,
                           t1src + (size_t)cc * HW, t1row_bytes, mb);
            }
        }
        t2src += (size_t)CC * HW;
        t1src += (size_t)CC * HW;
        if (++prod_stage == STAGES) prod_stage = 0;
    };

    issue();            // chunk 0 -> stage 0
    issue();            // chunk 1 -> stage 1

    int cs = 0, cph = 0;      // consumer stage / phase parity

    for (int it = 0; it < NCHUNK; it++) {
        mbar_wait(mb0 + cs * 8, cph);
        __syncthreads();              // all warps done with chunk it-1's stage
        if (it + 2 < NCHUNK) issue();

        const float* b_t1 = s_t1 + (size_t)cs * T1_STG;
        const float* b_t2 = s_t2 + (size_t)cs * T2_STG;

        #pragma unroll
        for (int cc = 0; cc < CC; cc++) {
            float4 a = *(const float4*)&b_t1[cc * XT + xl];
            u64 A0 = pk(a.x, a.y), A1 = pk(a.z, a.w);

            const float* tr = &b_t2[(cc * DD + wid) * T2C + xl];
            float4 v0 = *(const float4*)&tr[0];
            float4 v1 = *(const float4*)&tr[4];
            float4 v2 = *(const float4*)&tr[8];

            u64 P[6];
            P[0] = pk(v0.x, v0.y); P[1] = pk(v0.z, v0.w);
            P[2] = pk(v1.x, v1.y); P[3] = pk(v1.z, v1.w);
            P[4] = pk(v2.x, v2.y); P[5] = pk(v2.z, v2.w);
            u64 Q[5];
            Q[0] = pk(v0.y, v0.z); Q[1] = pk(v0.w, v1.x);
            Q[2] = pk(v1.y, v1.z); Q[3] = pk(v1.w, v2.x);
            Q[4] = pk(v2.y, v2.z);

            #pragma unroll
            for (int dj = 0; dj < DD; dj++) {
                const int h = dj >> 1;
                if ((dj & 1) == 0) {
                    fma2(acc[dj][0], A0, P[h + 0]);
                    fma2(acc[dj][1], A1, P[h + 1]);
                } else {
                    fma2(acc[dj][0], A0, Q[h + 0]);
                    fma2(acc[dj][1], A1, Q[h + 1]);
                }
            }
        }

        if (++cs == STAGES) { cs = 0; cph ^= 1; }
    }

    // ---- write out: p = wid*9 + dj ----
    size_t obase = (((size_t)batch * 81 + (size_t)wid * DD) * HH + y) * WW + x0 + xl;
    #pragma unroll
    for (int dj = 0; dj < DD; dj++) {
        float2 p0 = upk(acc[dj][0]), p1 = upk(acc[dj][1]);
        *(float4*)&out[obase + (size_t)dj * HW] = make_float4(p0.x, p0.y, p1.x, p1.y);
    }
}

extern "C" void kernel_launch(void* const* d_in, const int* in_sizes, int n_in,
                              void* d_out, int out_size)
{
    const float* t1 = (const float*)d_in[0];
    const float* t2 = (const float*)d_in[1];
    float* out = (float*)d_out;
    cudaFuncSetAttribute(corr_volume_kernel,
                         cudaFuncAttributeMaxDynamicSharedMemorySize, SMEM_BYTES);
    corr_volume_kernel<<<2 * 4 * HH, NTHREADS, SMEM_BYTES>>>(t1, t2, out);
}

// round 10
// speedup vs baseline: 1.5194x; 1.3581x over previous
#include <cuda_runtime.h>

// Local cost volume (SpatialCorrelationSampler, kernel_size=1, patch 9x9):
// out[b, p, y, x] = sum_c t1[b,c,y,x] * t2[b,c,y+di,x+dj],  p=(di+4)*9+(dj+4)
// t1,t2 [4,128,128,256] f32 -> out [4,81,128,256] f32.
//
// Block = (batch, y, x-tile of 128). 18 warps: warp (di, half) computes
// dj 0..4 (half 0) or dj 5..8 (half 1) for displacement row di.
// Per-thread: 4 px, <=10 packed f32x2 accumulators -> ~50 regs ->
// 2 CTAs x 576 thr = 36 warps/SM (56% occ). Per-SM crossbar / FMA / LDGSTS
// identical to the 9-warp version. 3-stage cp.async pipeline.

#define CH 128
#define HH 128
#define WW 256
#define MD 4
#define DD 9
#define CC 4
#define XT 128
#define T2C 136           // 34 granules of 4 floats
#define HW (HH*WW)
#define NTHREADS 576
#define NCHUNK 32
#define STAGES 3

#define T1_STG (CC*XT)          // 512 floats
#define T2_STG (CC*DD*T2C)      // 4896 floats
#define SMEM_BYTES (STAGES*(T1_STG+T2_STG)*4)   // 64,896 B

typedef unsigned long long u64;

__device__ __forceinline__ u64 pk(float lo, float hi) {
    u64 r; asm("mov.b64 %0, {%1,%2};" : "=l"(r) : "f"(lo), "f"(hi)); return r;
}
__device__ __forceinline__ void fma2(u64 &d, u64 a, u64 b) {
    asm("fma.rn.f32x2 %0, %1, %2, %0;" : "+l"(d) : "l"(a), "l"(b));
}
__device__ __forceinline__ float2 upk(u64 v) {
    float lo, hi; asm("mov.b64 {%0,%1}, %2;" : "=f"(lo), "=f"(hi) : "l"(v));
    return make_float2(lo, hi);
}
__device__ __forceinline__ void cpasync16(unsigned smem_addr, const void* gptr) {
    asm volatile("cp.async.cg.shared.global [%0], [%1], 16;" ::
                 "r"(smem_addr), "l"(gptr));
}

__global__ __launch_bounds__(NTHREADS, 2)
void corr_volume_kernel(const float* __restrict__ t1,
                        const float* __restrict__ t2,
                        float* __restrict__ out)
{
    extern __shared__ float sm[];
    float* s_t1 = sm;                       // [STAGES][CC][XT]
    float* s_t2 = sm + STAGES * T1_STG;     // [STAGES][CC][DD][T2C]

    const int tid   = threadIdx.x;
    const int w2    = tid >> 5;             // 0..17
    const int di    = w2 >> 1;              // 0..8
    const int half  = w2 & 1;               // 0: dj 0..4, 1: dj 5..8
    const int lane  = tid & 31;
    const int blk   = blockIdx.x;           // 0..1023
    const int xt    = blk & 1;
    const int y     = (blk >> 1) & (HH - 1);
    const int batch = blk >> 8;
    const int x0    = xt * XT;

    const int gy = y + di - MD;
    const bool vrow = (unsigned)gy < (unsigned)HH;     // warp-pair-uniform

    // halo: smem granule h holds gx = x0 + 4h - 4. valid h in [lo, lo+33),
    // one pad granule per row at hpad.
    const int lo   = (xt == 0) ? 1 : 0;
    const int hpad = (xt == 0) ? 0 : 33;

    // ---- one-time zero of constant pad regions (all stages) ----
    {
        const float4 z = make_float4(0.f, 0.f, 0.f, 0.f);
        #pragma unroll
        for (int st = 0; st < STAGES; st++)
            #pragma unroll
            for (int cc = 0; cc < CC; cc++) {
                float* row = s_t2 + (size_t)st * T2_STG + (cc * DD + di) * T2C;
                if (vrow) {
                    if (half == 0 && lane == 0)
                        *(float4*)&row[4 * hpad] = z;
                } else {
                    // whole row zero; half0 granules 0..16, half1 17..33
                    int g = (half ? 17 : 0) + lane;
                    if (lane < (half ? 17 : 17))
                        if (g < 34) *(float4*)&row[4 * g] = z;
                }
            }
    }

    u64 acc[5];
    #pragma unroll
    for (int k = 0; k < 5; k++) acc[k] = 0ull;
    u64 acc5[5];
    #pragma unroll
    for (int k = 0; k < 5; k++) acc5[k] = 0ull;
    // acc[k] covers px pair (2k mod 4) of dj group; we use acc[0..1] per dj:
    // layout: dj index d (0..4 or 0..3): acc[d] = px pair 0, acc5[d] = px pair 1.

    const int xl = lane * 4;

    // ---- fill assignments ----
    // t2: half0 fills granules h = lo+lane (lane<17); half1 h = lo+17+lane (lane<16)
    const int myh   = lo + (half ? 17 : 0) + lane;
    const bool fill2 = vrow && (lane < (half ? 16 : 17));
    const unsigned t2b = (unsigned)__cvta_generic_to_shared(s_t2);
    const unsigned t1b = (unsigned)__cvta_generic_to_shared(s_t1);
    const unsigned t2dst0 = t2b + (unsigned)(di * T2C + 4 * myh) * 4;
    const float* t2src0 = t2 + (size_t)batch * CH * HW
                             + (size_t)(vrow ? gy : 0) * WW + (x0 - 4 + 4 * myh);
    // t1: warps w2 in {0,2,4,6} fill channel cc = di (granule = lane)
    const bool fill1 = (half == 0) && (di < CC);
    const unsigned t1dst0 = t1b + (unsigned)(di * XT + 4 * lane) * 4;
    const float* t1src0 = t1 + (size_t)batch * CH * HW + (size_t)y * WW
                             + x0 + 4 * lane;

    auto issue = [&](int chunk) {
        const int c0 = chunk * CC;
        const int st = chunk % STAGES;
        if (fill2) {
            const float* src = t2src0 + (size_t)c0 * HW;
            const unsigned dst = t2dst0 + (unsigned)(st * T2_STG) * 4;
            #pragma unroll
            for (int cc = 0; cc < CC; cc++)
                cpasync16(dst + (unsigned)(cc * (DD * T2C)) * 4,
                          src + (size_t)cc * HW);
        }
        if (fill1)
            cpasync16(t1dst0 + (unsigned)(st * T1_STG) * 4,
                      t1src0 + (size_t)(c0 + di) * HW);
        asm volatile("cp.async.commit_group;");
    };

    issue(0);
    issue(1);

    const int woff = half ? 4 : 0;   // window float offset within lane's span

    for (int it = 0; it < NCHUNK; it++) {
        const int st = it % STAGES;
        if (it == NCHUNK - 1) asm volatile("cp.async.wait_group 0;");
        else                  asm volatile("cp.async.wait_group 1;");
        __syncthreads();              // chunk it visible; stage (it+2)%3 free
        if (it + 2 < NCHUNK) issue(it + 2);

        const float* b_t1 = s_t1 + (size_t)st * T1_STG;
        const float* b_t2 = s_t2 + (size_t)st * T2_STG;

        #pragma unroll
        for (int cc = 0; cc < CC; cc++) {
            float4 a = *(const float4*)&b_t1[cc * XT + xl];
            u64 A0 = pk(a.x, a.y), A1 = pk(a.z, a.w);

            const float* tr = &b_t2[(cc * DD + di) * T2C + xl + woff];
            float4 va = *(const float4*)&tr[0];
            float4 vb = *(const float4*)&tr[4];

            // aligned pairs (free from LDS.128), odd packs (movs)
            u64 Pa = pk(va.x, va.y), Pb = pk(va.z, va.w);
            u64 Pc = pk(vb.x, vb.y), Pd = pk(vb.z, vb.w);
            u64 Qa = pk(va.y, va.z), Qb = pk(va.w, vb.x);
            u64 Qc = pk(vb.y, vb.z);

            if (half == 0) {
                // dj0: Pa,Pb  dj1: Qa,Qb  dj2: Pb,Pc  dj3: Qb,Qc  dj4: Pc,Pd
                fma2(acc[0],  A0, Pa); fma2(acc5[0], A1, Pb);
                fma2(acc[1],  A0, Qa); fma2(acc5[1], A1, Qb);
                fma2(acc[2],  A0, Pb); fma2(acc5[2], A1, Pc);
                fma2(acc[3],  A0, Qb); fma2(acc5[3], A1, Qc);
                fma2(acc[4],  A0, Pc); fma2(acc5[4], A1, Pd);
            } else {
                // window floats g0..g7 = global f4..f11
                // dj5: Qa,Qb  dj6: Pb,Pc  dj7: Qb,Qc  dj8: Pc,Pd
                fma2(acc[0],  A0, Qa); fma2(acc5[0], A1, Qb);
                fma2(acc[1],  A0, Pb); fma2(acc5[1], A1, Pc);
                fma2(acc[2],  A0, Qb); fma2(acc5[2], A1, Qc);
                fma2(acc[3],  A0, Pc); fma2(acc5[3], A1, Pd);
            }
        }
    }

    // ---- write out: p = di*9 + dj ----
    const int ndj = half ? 4 : 5;
    const int dj0 = half ? 5 : 0;
    size_t obase = (((size_t)batch * 81 + (size_t)di * DD + dj0) * HH + y) * WW
                 + x0 + xl;
    #pragma unroll
    for (int d = 0; d < 5; d++) {
        if (d < ndj) {
            float2 p0 = upk(acc[d]), p1 = upk(acc5[d]);
            *(float4*)&out[obase + (size_t)d * HW] =
                make_float4(p0.x, p0.y, p1.x, p1.y);
        }
    }
}

extern "C" void kernel_launch(void* const* d_in, const int* in_sizes, int n_in,
                              void* d_out, int out_size)
{
    const float* t1 = (const float*)d_in[0];
    const float* t2 = (const float*)d_in[1];
    float* out = (float*)d_out;
    cudaFuncSetAttribute(corr_volume_kernel,
                         cudaFuncAttributeMaxDynamicSharedMemorySize, SMEM_BYTES);
    corr_volume_kernel<<<2 * 4 * HH, NTHREADS, SMEM_BYTES>>>(t1, t2, out);
}

// round 11
// speedup vs baseline: 1.9099x; 1.2570x over previous
#include <cuda_runtime.h>

// Local cost volume (SpatialCorrelationSampler, kernel_size=1, patch 9x9):
// out[b, p, y, x] = sum_c t1[b,c,y,x] * t2[b,c,y+di,x+dj],  p=(di+4)*9+(dj+4)
// t1,t2 [4,128,128,256] f32 -> out [4,81,128,256] f32.
//
// Small-CTA variant of the best (R4) kernel: CTA = 96 threads = 3 warps,
// covering ONE x-tile of 128 px and THREE di rows (blockIdx.y selects the
// di-group). Per-warp instruction stream identical to R4 (4 px/lane, packed
// fma.rn.f32x2, 18 u64 acc, 3 t2 + 1 t1 LDS.128 per channel). 10 CTAs/SM
// (launch_bounds(96,10)) -> 30 warps = 47% occupancy with tiny 3-warp
// barriers and fully decoupled CTAs.

#define CH 128
#define HH 128
#define WW 256
#define MD 4
#define DD 9
#define NDI 3             // di rows per CTA
#define CC 4
#define XT 128
#define T2C 136           // 34 granules of 4 floats
#define HW (HH*WW)
#define NTHREADS 96
#define NCHUNK 32
#define STAGES 2

#define T1_STG (CC*XT)          // 512 floats
#define T2_STG (CC*NDI*T2C)     // 1632 floats
#define SMEM_BYTES (STAGES*(T1_STG+T2_STG)*4)   // 17,152 B

typedef unsigned long long u64;

__device__ __forceinline__ u64 pk(float lo, float hi) {
    u64 r; asm("mov.b64 %0, {%1,%2};" : "=l"(r) : "f"(lo), "f"(hi)); return r;
}
__device__ __forceinline__ void fma2(u64 &d, u64 a, u64 b) {
    asm("fma.rn.f32x2 %0, %1, %2, %0;" : "+l"(d) : "l"(a), "l"(b));
}
__device__ __forceinline__ float2 upk(u64 v) {
    float lo, hi; asm("mov.b64 {%0,%1}, %2;" : "=f"(lo), "=f"(hi) : "l"(v));
    return make_float2(lo, hi);
}
__device__ __forceinline__ void cpasync16(unsigned smem_addr, const void* gptr) {
    asm volatile("cp.async.cg.shared.global [%0], [%1], 16;" ::
                 "r"(smem_addr), "l"(gptr));
}

__global__ __launch_bounds__(NTHREADS, 10)
void corr_volume_kernel(const float* __restrict__ t1,
                        const float* __restrict__ t2,
                        float* __restrict__ out)
{
    extern __shared__ float sm[];
    float* s_t1 = sm;                       // [STAGES][CC][XT]
    float* s_t2 = sm + STAGES * T1_STG;     // [STAGES][CC][NDI][T2C]

    const int tid   = threadIdx.x;
    const int wid   = tid >> 5;             // 0..2 within CTA
    const int lane  = tid & 31;
    const int blk   = blockIdx.x;           // 0..1023
    const int xt    = blk & 1;
    const int y     = (blk >> 1) & (HH - 1);
    const int batch = blk >> 8;
    const int x0    = xt * XT;
    const int di    = blockIdx.y * NDI + wid;   // 0..8

    const int gy = y + di - MD;
    const bool vrow = (unsigned)gy < (unsigned)HH;     // warp-uniform

    // halo: smem col j holds gx = x0 + j - 4. valid granules h in [lo, lo+33),
    // one pad granule per row at hpad.
    const int lo   = (xt == 0) ? 1 : 0;
    const int hpad = (xt == 0) ? 0 : 33;

    // ---- one-time zero of constant pad regions (both stages) ----
    // t2 row (cc, wid) is written AND read only by warp wid -> syncwarp-safe.
    {
        const float4 z = make_float4(0.f, 0.f, 0.f, 0.f);
        #pragma unroll
        for (int st = 0; st < STAGES; st++)
            #pragma unroll
            for (int cc = 0; cc < CC; cc++) {
                float* row = s_t2 + (size_t)st * T2_STG + (cc * NDI + wid) * T2C;
                if (vrow) {
                    if (lane == 0) *(float4*)&row[4 * hpad] = z;
                } else {
                    *(float4*)&row[4 * lane] = z;               // granules 0..31
                    if (lane < 2) *(float4*)&row[4 * (32 + lane)] = z;
                }
            }
    }

    u64 acc[DD][2];
    #pragma unroll
    for (int d = 0; d < DD; d++) { acc[d][0] = 0ull; acc[d][1] = 0ull; }

    const int xl = lane * 4;

    // ---- copy target addresses (stage 0) ----
    // t2: warp fills its own row; lane -> granule lo+lane, lane0 also lo+32.
    const unsigned t2b = (unsigned)__cvta_generic_to_shared(s_t2);
    const unsigned t1b = (unsigned)__cvta_generic_to_shared(s_t1);
    const unsigned t2d1 = t2b + (unsigned)(wid * T2C + 4 * (lo + lane)) * 4;
    const unsigned t2d2 = t2b + (unsigned)(wid * T2C + 4 * (lo + 32)) * 4;
    const float* t2src = t2 + (size_t)batch * CH * HW
                            + (size_t)(vrow ? gy : 0) * WW + (x0 - 4 + 4 * lo);
    // t1: thread tid fills granule g=tid (cc=g>>5), tid<32 also g2=96+tid (cc=3).
    const int g1 = tid, g2 = 96 + tid;
    const unsigned t1d1 = t1b + (unsigned)((g1 >> 5) * XT + 4 * (g1 & 31)) * 4;
    const unsigned t1d2 = t1b + (unsigned)((g2 >> 5) * XT + 4 * (g2 & 31)) * 4;
    const float* t1row = t1 + (size_t)batch * CH * HW + (size_t)y * WW + x0;
    const float* t1s1 = t1row + (size_t)(g1 >> 5) * HW + 4 * (g1 & 31);
    const float* t1s2 = t1row + (size_t)(g2 >> 5) * HW + 4 * (g2 & 31);

    auto issue = [&](int chunk) {
        const int c0 = chunk * CC;
        const unsigned stoff = (chunk & 1) ? 1u : 0u;
        if (vrow) {
            const float* src = t2src + (size_t)c0 * HW;
            const unsigned so = stoff * (T2_STG * 4);
            #pragma unroll
            for (int cc = 0; cc < CC; cc++) {
                const unsigned co = so + (unsigned)(cc * (NDI * T2C)) * 4;
                cpasync16(t2d1 + co, src + (size_t)cc * HW + 4 * lane);
                if (lane == 0) cpasync16(t2d2 + co, src + (size_t)cc * HW + 128);
            }
        }
        {
            const unsigned so = stoff * (T1_STG * 4);
            cpasync16(t1d1 + so, t1s1 + (size_t)c0 * HW);
            if (tid < 32) cpasync16(t1d2 + so, t1s2 + (size_t)c0 * HW);
        }
        asm volatile("cp.async.commit_group;");
    };

    issue(0);

    for (int it = 0; it < NCHUNK; it++) {
        const int st = it & 1;
        asm volatile("cp.async.wait_group 0;");
        __syncthreads();               // chunk `it` visible; other stage free
        if (it + 1 < NCHUNK) issue(it + 1);

        const float* b_t1 = s_t1 + (size_t)st * T1_STG;
        const float* b_t2 = s_t2 + (size_t)st * T2_STG;

        #pragma unroll
        for (int cc = 0; cc < CC; cc++) {
            float4 a = *(const float4*)&b_t1[cc * XT + xl];
            u64 A0 = pk(a.x, a.y), A1 = pk(a.z, a.w);

            const float* tr = &b_t2[(cc * NDI + wid) * T2C + xl];
            float4 v0 = *(const float4*)&tr[0];
            float4 v1 = *(const float4*)&tr[4];
            float4 v2 = *(const float4*)&tr[8];

            u64 P[6];
            P[0] = pk(v0.x, v0.y); P[1] = pk(v0.z, v0.w);
            P[2] = pk(v1.x, v1.y); P[3] = pk(v1.z, v1.w);
            P[4] = pk(v2.x, v2.y); P[5] = pk(v2.z, v2.w);
            u64 Q[5];
            Q[0] = pk(v0.y, v0.z); Q[1] = pk(v0.w, v1.x);
            Q[2] = pk(v1.y, v1.z); Q[3] = pk(v1.w, v2.x);
            Q[4] = pk(v2.y, v2.z);

            #pragma unroll
            for (int dj = 0; dj < DD; dj++) {
                const int h = dj >> 1;
                if ((dj & 1) == 0) {
                    fma2(acc[dj][0], A0, P[h + 0]);
                    fma2(acc[dj][1], A1, P[h + 1]);
                } else {
                    fma2(acc[dj][0], A0, Q[h + 0]);
                    fma2(acc[dj][1], A1, Q[h + 1]);
                }
            }
        }
    }

    // ---- write out: p = di*9 + dj ----
    size_t obase = (((size_t)batch * 81 + (size_t)di * DD) * HH + y) * WW + x0 + xl;
    #pragma unroll
    for (int dj = 0; dj < DD; dj++) {
        float2 p0 = upk(acc[dj][0]), p1 = upk(acc[dj][1]);
        *(float4*)&out[obase + (size_t)dj * HW] = make_float4(p0.x, p0.y, p1.x, p1.y);
    }
}

extern "C" void kernel_launch(void* const* d_in, const int* in_sizes, int n_in,
                              void* d_out, int out_size)
{
    const float* t1 = (const float*)d_in[0];
    const float* t2 = (const float*)d_in[1];
    float* out = (float*)d_out;
    cudaFuncSetAttribute(corr_volume_kernel,
                         cudaFuncAttributeMaxDynamicSharedMemorySize, SMEM_BYTES);
    dim3 grid(2 * 4 * HH, DD / NDI);
    corr_volume_kernel<<<grid, NTHREADS, SMEM_BYTES>>>(t1, t2, out);
}